// round 10
// baseline (speedup 1.0000x reference)
#include <cuda_runtime.h>
#include <cuda_bf16.h>

#define B_    512
#define BAG_  32
#define H_    1024
#define C_    53
#define N_    (B_*BAG_)   // 16384
#define EPS_  1e-8f
#define NSLOT 16

// ---------------- device scratch ----------------
__device__ __align__(128) __nv_bfloat16 g_rep_bf[N_*H_];
__device__ __align__(128) __nv_bfloat16 g_bag_bf[B_*H_];
__device__ float g_rnb[B_];
__device__ float g_rnr[N_];
__device__ float g_pos[N_];
__device__ float g_negp[NSLOT][N_];
__device__ float g_lsum;
__device__ int   g_cnt  = 0;
__device__ int   g_sctr = 0;    // sample work counter (phase A)
__device__ int   g_tctr = 0;    // tile work counter (phase B)
__device__ int   g_flag[B_];    // per-sample completion flags

__device__ __forceinline__ float warp_sum(float v) {
    #pragma unroll
    for (int o = 16; o; o >>= 1) v += __shfl_down_sync(0xffffffffu, v, o);
    return v;
}
__device__ __forceinline__ float warp_max(float v) {
    #pragma unroll
    for (int o = 16; o; o >>= 1) v = fmaxf(v, __shfl_xor_sync(0xffffffffu, v, o));
    return v;
}

// fast exp on the FMA pipe: no MUFU, no CVT. |x| <= 20, rel err < 3e-6.
__device__ __forceinline__ float fexp(float x) {
    const float LOG2E = 1.4426950408889634f;
    float z = fmaf(x, LOG2E, 12582912.0f);
    int   iz = __float_as_int(z);
    float r  = z - 12582912.0f;
    float f  = fmaf(x, LOG2E, -r);
    float p =            1.3298820e-3f;
    p = fmaf(p, f, 9.6179670e-3f);
    p = fmaf(p, f, 5.5503645e-2f);
    p = fmaf(p, f, 2.4022645e-1f);
    p = fmaf(p, f, 6.9314718e-1f);
    p = fmaf(p, f, 1.0f);
    unsigned sc = ((unsigned)iz + (127u - 0x4B400000u)) << 23;
    return p * __int_as_float(sc);
}

// ---------------- PTX helpers ----------
#define MBAR_INIT(addr, cnt) \
    asm volatile("mbarrier.init.shared.b64 [%0], %1;" :: "r"(addr), "r"(cnt) : "memory")

#define MBAR_WAIT(addr, par) do {                                              \
    unsigned _m = (addr), _p = (par), _d;                                      \
    asm volatile("{\n\t.reg .pred p;\n\t"                                      \
        "mbarrier.try_wait.parity.acquire.cta.shared::cta.b64 p, [%1], %2;\n\t"\
        "selp.b32 %0,1,0,p;\n\t}" : "=r"(_d) : "r"(_m), "r"(_p) : "memory");   \
    if (!_d) {                                                                 \
        asm volatile("{\n\t.reg .pred P1;\n\t"                                 \
        "WL_%=:\n\t"                                                           \
        "mbarrier.try_wait.parity.acquire.cta.shared::cta.b64 P1, [%0], %1, 0x989680;\n\t" \
        "@P1 bra.uni WD_%=;\n\t"                                               \
        "bra.uni WL_%=;\n\t"                                                   \
        "WD_%=:\n\t}" :: "r"(_m), "r"(_p) : "memory");                         \
    }                                                                          \
} while (0)

#define MBAR_ARRIVE(addr) \
    asm volatile("mbarrier.arrive.shared.b64 _, [%0];" :: "r"(addr) : "memory")

#define LDSM4(r, addr) \
    asm volatile("ldmatrix.sync.aligned.m8n8.x4.shared.b16 {%0,%1,%2,%3}, [%4];" \
        : "=r"((r)[0]), "=r"((r)[1]), "=r"((r)[2]), "=r"((r)[3]) : "r"(addr))

#define MMA_BF16(c, a, b0v, b1v) \
    asm volatile("mma.sync.aligned.m16n8k16.row.col.f32.bf16.bf16.f32 " \
        "{%0,%1,%2,%3}, {%4,%5,%6,%7}, {%8,%9}, {%0,%1,%2,%3};" \
        : "+f"((c)[0]), "+f"((c)[1]), "+f"((c)[2]), "+f"((c)[3]) \
        : "r"((a)[0]), "r"((a)[1]), "r"((a)[2]), "r"((a)[3]), "r"(b0v), "r"(b1v))

__device__ __forceinline__ void bulk_cp(unsigned dst, const void* src,
                                        unsigned bytes, unsigned mbar) {
    asm volatile(
        "cp.async.bulk.shared::cta.global.mbarrier::complete_tx::bytes [%0], [%1], %2, [%3];"
        :: "r"(dst), "l"(src), "r"(bytes), "r"(mbar) : "memory");
}
__device__ __forceinline__ void mbar_expect(unsigned mbar, unsigned bytes) {
    asm volatile("mbarrier.arrive.expect_tx.shared.b64 _, [%0], %1;"
                 :: "r"(mbar), "r"(bytes) : "memory");
}
__device__ __forceinline__ unsigned sw128(unsigned byo) {
    return byo ^ ((byo >> 3) & 0x70);
}
__device__ __forceinline__ unsigned bf2u(__nv_bfloat162 h) {
    return *(unsigned*)&h;
}

// ---------------- fused persistent kernel: phase A (samples) + phase B (tiles)
#define STAGES 3
#define STAGE_BYTES 32768
#define NKC 16
#define PAIR_SMEM (STAGES * STAGE_BYTES)   // 98304

__global__ void __launch_bounds__(256, 2) k_fused(
    const float* __restrict__ rep, const float* __restrict__ aug,
    const float* __restrict__ rel_table, const int* __restrict__ labels,
    const float* __restrict__ cls_w, const float* __restrict__ cls_b,
    float* __restrict__ out, const float* __restrict__ tptr)
{
    extern __shared__ __align__(16) char smem[];
    __shared__ __align__(8) unsigned long long mbars[2 * STAGES];
    __shared__ float s_scores[BAG_];
    __shared__ float s_alpha[BAG_];
    __shared__ float s_red[8];
    __shared__ int   s_work;

    unsigned smem_u = (unsigned)__cvta_generic_to_shared(smem);
    unsigned mbar_u = (unsigned)__cvta_generic_to_shared(mbars);
    int tid = threadIdx.x, wid = tid >> 5, lane = tid & 31;
    float invT = 1.0f / tptr[0];

    if (tid == 0) {
        #pragma unroll
        for (int s = 0; s < STAGES; ++s) {
            MBAR_INIT(mbar_u + 8 * s, 1);              // full: tx-based
            MBAR_INIT(mbar_u + 8 * (STAGES + s), 8);   // empty: 8 warp arrivals
        }
    }
    __syncthreads();

    // ================= PHASE A: samples =================
    for (;;) {
        __syncthreads();
        if (tid == 0) s_work = atomicAdd(&g_sctr, 1);
        __syncthreads();
        int b = s_work;
        if (b >= B_) break;

        const float* repb = rep + (size_t)b * BAG_ * H_;
        const float4* rel4 = (const float4*)(rel_table + (size_t)labels[b] * H_);

        // zero neg slots for this sample; reset loss scalar
        #pragma unroll
        for (int q = 0; q < 2; ++q)
            g_negp[wid + q * 8][b * BAG_ + lane] = 0.0f;
        if (b == 0 && tid == 0) g_lsum = 0.0f;

        // each warp: 4 sentences — scores, norms, pos, bf16 staging
        for (int j = wid; j < BAG_; j += 8) {
            int n = b * BAG_ + j;
            const float4* r4 = (const float4*)(repb + (size_t)j * H_);
            const float4* a4 = (const float4*)(aug + (size_t)n * H_);
            char* dstb = (char*)g_rep_bf + (size_t)(n >> 3) * 1024;
            unsigned inoff = sw128((unsigned)(n & 7) * 128u + (unsigned)(lane & 15) * 8u);
            float ds = 0.f, dr = 0.f, da = 0.f, dra = 0.f;
            #pragma unroll
            for (int i = 0; i < 8; ++i) {
                int t = lane + 32 * i;
                float4 rv = r4[t], av = a4[t], rl = rel4[t];
                uint2 pk;
                pk.x = bf2u(__floats2bfloat162_rn(rv.x, rv.y));
                pk.y = bf2u(__floats2bfloat162_rn(rv.z, rv.w));
                unsigned kc = (unsigned)(lane >> 4) + 2u * i;
                *(uint2*)(dstb + (size_t)kc * (N_ * 128) + inoff) = pk;
                ds  = fmaf(rl.x, rv.x, fmaf(rl.y, rv.y, fmaf(rl.z, rv.z, fmaf(rl.w, rv.w, ds))));
                dr  = fmaf(rv.x, rv.x, fmaf(rv.y, rv.y, fmaf(rv.z, rv.z, fmaf(rv.w, rv.w, dr))));
                da  = fmaf(av.x, av.x, fmaf(av.y, av.y, fmaf(av.z, av.z, fmaf(av.w, av.w, da))));
                dra = fmaf(rv.x, av.x, fmaf(rv.y, av.y, fmaf(rv.z, av.z, fmaf(rv.w, av.w, dra))));
            }
            ds = warp_sum(ds); dr = warp_sum(dr); da = warp_sum(da); dra = warp_sum(dra);
            if (lane == 0) {
                s_scores[j] = ds * (1.0f / 32.0f);      // / sqrt(H)
                float nr = sqrtf(dr), na = sqrtf(da);
                g_rnr[n] = 1.0f / nr;
                float psim = dra / fmaxf(nr * na, EPS_);
                g_pos[n] = expf(psim * invT);
            }
        }
        __syncthreads();

        if (tid < 32) {
            float v = s_scores[tid];
            float m = warp_max(v);
            float e = expf(v - m);
            float s = warp_sum(e);
            s = __shfl_sync(0xffffffffu, s, 0);
            s_alpha[tid] = e / s;
        }
        __syncthreads();

        // pooling: one float4 per thread; rows L1/L2-hot from the score pass
        float4* sbag = (float4*)smem;                    // 4 KB scratch
        const float4* rp4 = (const float4*)repb;
        float4 acc = make_float4(0.f, 0.f, 0.f, 0.f);
        #pragma unroll 8
        for (int j = 0; j < BAG_; ++j) {
            float4 v = rp4[(size_t)j * 256 + tid];
            float a = s_alpha[j];
            acc.x = fmaf(a, v.x, acc.x); acc.y = fmaf(a, v.y, acc.y);
            acc.z = fmaf(a, v.z, acc.z); acc.w = fmaf(a, v.w, acc.w);
        }
        sbag[tid] = acc;
        {
            uint2 pk;
            pk.x = bf2u(__floats2bfloat162_rn(acc.x, acc.y));
            pk.y = bf2u(__floats2bfloat162_rn(acc.z, acc.w));
            unsigned kc = (unsigned)tid >> 4;
            unsigned sw = sw128((unsigned)(b & 7) * 128u + (unsigned)(tid & 15) * 8u);
            *(uint2*)((char*)g_bag_bf + (size_t)kc * (B_ * 128) + (size_t)(b >> 3) * 1024 + sw) = pk;
        }
        float nb_part = fmaf(acc.x, acc.x, fmaf(acc.y, acc.y, fmaf(acc.z, acc.z, acc.w * acc.w)));
        nb_part = warp_sum(nb_part);
        if (lane == 0) s_red[wid] = nb_part;
        __syncthreads();
        if (tid == 0) {
            float s = 0.f;
            #pragma unroll
            for (int w = 0; w < 8; ++w) s += s_red[w];
            g_rnb[b] = 1.0f / sqrtf(s);
            __threadfence();                 // release all sample-b writes
            *(volatile int*)&g_flag[b] = 1;  // publish (tiles may start)
        }
        // classifier row for sample b (bag vector is in smem)
        for (int c = wid; c < C_; c += 8) {
            const float4* w4 = (const float4*)(cls_w + (size_t)c * H_);
            float a = 0.f;
            for (int i = lane; i < 256; i += 32) {
                float4 wv = w4[i], bv = sbag[i];
                a = fmaf(wv.x, bv.x, fmaf(wv.y, bv.y, fmaf(wv.z, bv.z, fmaf(wv.w, bv.w, a))));
            }
            a = warp_sum(a);
            if (lane == 0) out[b * C_ + c] = a + cls_b[c];
        }
    }

    // ================= PHASE B: GEMM tiles =================
    int wm = wid >> 2, wn = wid & 3;
    unsigned xr   = (unsigned)(lane & 7) * 16u;
    unsigned hk16 = (unsigned)(lane >> 4) * 16u;
    unsigned kb16 = (unsigned)((lane >> 3) & 1) * 16u;
    unsigned aoffb = (unsigned)((wm * 64 + (lane & 15)) * 128);
    unsigned boffb = (unsigned)((wn * 32 + ((lane >> 4) & 1) * 8 + (lane & 7)) * 128) + 16384u;

    const char* Asrc = (const char*)g_bag_bf;
    const char* Bsrc = (const char*)g_rep_bf;
    int T = 0;   // tiles processed by this CTA (drives mbarrier parity bases)

    for (;;) {
        __syncthreads();
        if (tid == 0) s_work = atomicAdd(&g_tctr, 1);
        __syncthreads();
        int t = s_work;
        if (t >= 512) break;
        int m0 = (t & 3) * 128, n0 = (t >> 2) * 128;

        // wait for the producing samples (producers are co-resident: safe)
        if (tid < 128) {
            volatile int* f = &g_flag[m0 + tid];
            while (*f == 0) __nanosleep(64);
        } else if (tid < 132) {
            volatile int* f = &g_flag[(n0 >> 5) + (tid - 128)];
            while (*f == 0) __nanosleep(64);
        }
        __syncthreads();
        __threadfence();

        // prologue: fill 3 chunks. stage0 fill# = 6T, stage1/2 fill# = 5T.
        if (tid == 0) {
            asm volatile("fence.proxy.async;" ::: "memory");
            #pragma unroll
            for (int s = 0; s < STAGES; ++s) {
                if (T > 0) {
                    unsigned ep = (s == 0) ? 1u : ((unsigned)(T & 1) ^ 1u);
                    MBAR_WAIT(mbar_u + 8 * (STAGES + s), ep);
                }
                unsigned mb = mbar_u + 8 * s;
                mbar_expect(mb, 2 * 16384u);
                unsigned d = smem_u + s * STAGE_BYTES;
                bulk_cp(d,          Asrc + ((size_t)s * B_ + m0) * 128, 16384u, mb);
                bulk_cp(d + 16384u, Bsrc + ((size_t)s * N_ + n0) * 128, 16384u, mb);
            }
        }

        float acc[4][4][4] = {};

        #pragma unroll 1
        for (int kc = 0; kc < NKC; ++kc) {
            int st = kc % 3;
            unsigned u = (unsigned)(kc / 3);
            unsigned par = ((st == 0 ? 0u : (unsigned)(T & 1)) + u) & 1u;
            MBAR_WAIT(mbar_u + 8 * st, par);
            unsigned base = smem_u + st * STAGE_BYTES;
            #pragma unroll
            for (int ks = 0; ks < 4; ++ks) {
                unsigned afr[4][4], bfr[2][4];
                unsigned ksa = ((unsigned)(ks * 32) + hk16) ^ xr;
                unsigned ksb = ((unsigned)(ks * 32) + kb16) ^ xr;
                #pragma unroll
                for (int mt = 0; mt < 4; ++mt)
                    LDSM4(afr[mt], base + aoffb + mt * 2048u + ksa);
                #pragma unroll
                for (int np = 0; np < 2; ++np)
                    LDSM4(bfr[np], base + boffb + np * 2048u + ksb);
                #pragma unroll
                for (int mt = 0; mt < 4; ++mt)
                    #pragma unroll
                    for (int nt = 0; nt < 4; ++nt)
                        MMA_BF16(acc[mt][nt], afr[mt],
                                 bfr[nt >> 1][(nt & 1) * 2], bfr[nt >> 1][(nt & 1) * 2 + 1]);
            }
            if (lane == 0) MBAR_ARRIVE(mbar_u + 8 * (STAGES + st));
            if (kc + STAGES < NKC && wid == (kc & 7) && lane == 0) {
                MBAR_WAIT(mbar_u + 8 * (STAGES + st), par);
                unsigned mb = mbar_u + 8 * st;
                mbar_expect(mb, 2 * 16384u);
                unsigned d = smem_u + st * STAGE_BYTES;
                bulk_cp(d,          Asrc + ((size_t)(kc + STAGES) * B_ + m0) * 128, 16384u, mb);
                bulk_cp(d + 16384u, Bsrc + ((size_t)(kc + STAGES) * N_ + n0) * 128, 16384u, mb);
            }
        }
        __syncthreads();

        // epilogue: FMA-pipe exp, single-pass smem reduce, slotted atomics
        float* sbuf  = (float*)smem;                    // [4][128][33]
        float* s_rnr = (float*)(smem + 67584);
        float* s_rnb = (float*)(smem + 67584 + 512);
        if (tid < 128) { s_rnr[tid] = g_rnr[n0 + tid]; s_rnb[tid] = g_rnb[m0 + tid]; }
        __syncthreads();
        int bglob = (n0 >> 5) + wn;
        int r0base = wm * 64 + (lane >> 2);
        float* negslot = g_negp[t & (NSLOT - 1)];
        float* wbuf = sbuf + wn * (128 * 33);

        #pragma unroll
        for (int mt = 0; mt < 4; ++mt) {
            int r0 = r0base + mt * 16, r1 = r0 + 8;
            float f0 = s_rnb[r0] * invT, f1 = s_rnb[r1] * invT;
            bool sk0 = (m0 + r0) == bglob, sk1 = (m0 + r1) == bglob;
            #pragma unroll
            for (int nt = 0; nt < 4; ++nt) {
                int jj = nt * 8 + (lane & 3) * 2;
                float rn0 = s_rnr[wn * 32 + jj], rn1 = s_rnr[wn * 32 + jj + 1];
                float e00 = sk0 ? 0.f : fexp(acc[mt][nt][0] * f0 * rn0);
                float e01 = sk0 ? 0.f : fexp(acc[mt][nt][1] * f0 * rn1);
                float e10 = sk1 ? 0.f : fexp(acc[mt][nt][2] * f1 * rn0);
                float e11 = sk1 ? 0.f : fexp(acc[mt][nt][3] * f1 * rn1);
                wbuf[r0 * 33 + jj]     = e00;
                wbuf[r0 * 33 + jj + 1] = e01;
                wbuf[r1 * 33 + jj]     = e10;
                wbuf[r1 * 33 + jj + 1] = e11;
            }
        }
        __syncthreads();
        for (int e = tid; e < 4096; e += 256) {
            int lc = e >> 5, jj = e & 31;
            float v = sbuf[lc * 33 + jj]
                    + sbuf[1 * (128 * 33) + lc * 33 + jj]
                    + sbuf[2 * (128 * 33) + lc * 33 + jj]
                    + sbuf[3 * (128 * 33) + lc * 33 + jj];
            atomicAdd(&negslot[(m0 + lc) * BAG_ + jj], v);
        }
        __syncthreads();
        ++T;
    }
}

// ---------------- K4: loss + state reset (runs after k_fused) --------------
__global__ void __launch_bounds__(256) k_loss(const float* __restrict__ pos,
                                              float* __restrict__ out, int loss_idx) {
    int i = blockIdx.x * 256 + threadIdx.x;
    if (i < B_) g_flag[i] = 0;
    if (i == 0) { g_sctr = 0; g_tctr = 0; }
    float t = 0.f;
    #pragma unroll
    for (int s = 0; s < NSLOT; ++s) t += g_negp[s][i];
    float v = __logf(1.0f + __fdividef(t, pos[i]));
    v = warp_sum(v);
    __shared__ float sr[8];
    if ((threadIdx.x & 31) == 0) sr[threadIdx.x >> 5] = v;
    __syncthreads();
    if (threadIdx.x == 0) {
        float s = 0.f;
        #pragma unroll
        for (int w = 0; w < 8; ++w) s += sr[w];
        atomicAdd(&g_lsum, s);
        __threadfence();
        if (atomicAdd(&g_cnt, 1) == (N_ / 256) - 1) {
            out[loss_idx] = g_lsum * (1.0f / (float)N_);
            g_cnt = 0;
        }
    }
}

// ---------------- launch ----------------
extern "C" void kernel_launch(void* const* d_in, const int* in_sizes, int n_in,
                              void* d_out, int out_size) {
    const float* rep    = (const float*)d_in[0];
    const float* aug    = (const float*)d_in[1];
    const float* rel    = (const float*)d_in[2];
    const float* cls_w  = (const float*)d_in[3];
    const float* cls_b  = (const float*)d_in[4];
    const int*   labels = (const int*)d_in[5];
    const float* temp   = (const float*)d_in[6];
    float* out = (float*)d_out;

    static int grid2 = 0;
    if (!grid2) {
        cudaFuncSetAttribute(k_fused, cudaFuncAttributeMaxDynamicSharedMemorySize, PAIR_SMEM);
        int nsm = 0;
        cudaDeviceGetAttribute(&nsm, cudaDevAttrMultiProcessorCount, 0);
        grid2 = 2 * nsm;                 // exactly one wave: all CTAs co-resident
    }

    k_fused<<<grid2, 256, PAIR_SMEM>>>(rep, aug, rel, labels, cls_w, cls_b, out, temp);

    float* g_pos_ptr = nullptr;
    cudaGetSymbolAddress((void**)&g_pos_ptr, g_pos);
    k_loss<<<N_ / 256, 256>>>(g_pos_ptr, out, out_size - 1);
}